// round 13
// baseline (speedup 1.0000x reference)
#include <cuda_runtime.h>
#include <math.h>

// Problem constants (must match reference)
#define BB 16
#define HH 120
#define WW 160
#define DD 401              // int(8000/20)+1
#define NT 512              // threads per block
#define NB 300              // 300*512*2 = 307200 = B*H*W exactly (2 pixels/thread)
#define NPIX (BB * HH * WW)
#define DEPTH_MAX 8000.0f
#define INV_BIN   (1.0f / 20.0f)
#define BIN_SIZE  20.0f
#define ZERO_EPS  1e-06f
#define SIG_EPS   (0.5f + 1e-08f)

// fp32 sparsity: the Gaussian underflows to exactly 0 unless |k*20 - d| < ~7.2;
// bins are 20 apart -> only the rounded-nearest bin k = round(d/20) can be
// nonzero. For valid d in (eps, 8000], k is in [0,400]: no clamp needed.
// (d > eps && d <= max) also rejects NaN/Inf.
//
// Structure (r13): the zero phase moves OUT of the kernel into a
// cudaMemsetAsync graph node (driver fill at LTS rate, ~0.4us exec). The
// kernel is then pure scatter -- LDG -> EX2 -> RED.E.ADD.F32 -- with NO
// barrier and NO stores; the graph edge (memset -> kernel) provides the
// zeros-before-atomics ordering. Flat one-pixel-per-slot indexing over the
// contiguous (B,H,W) depth array: fully coalesced, zero predication waste.
// 300 blocks x 16 warps = 4800 warps, one shallow wave.

__global__ void __launch_bounds__(NT)
dim_scatter_kernel(const float* __restrict__ depth, float* __restrict__ out)
{
    const float inv_sig = 1.0f / SIG_EPS;                 // 1/(sigma+eps)
    const float norm    = 0.3989422804014327f * inv_sig;  // 1/((sigma+eps)*sqrt(2pi))

    // two pixels per thread, NB*NT apart (both coalesced across the block)
    const int p0 = blockIdx.x * NT + threadIdx.x;         // < 153600
    const float d0 = __ldg(depth + p0);
    const float d1 = __ldg(depth + p0 + NB * NT);         // < 307200

    #pragma unroll
    for (int i = 0; i < 2; ++i) {
        const int   p = i == 0 ? p0 : p0 + NB * NT;
        const float d = i == 0 ? d0 : d1;
        if (d > ZERO_EPS && d <= DEPTH_MAX) {             // also rejects NaN/Inf
            // p -> (b, h, w): depth is (B,H,W) contiguous
            int w  = p % WW;
            int bh = p / WW;                              // b*HH + h
            int b  = bh / HH;
            int k  = __float2int_rn(d * INV_BIN);         // nearest bin, [0,400]
            float z = ((float)k * BIN_SIZE - d) * inv_sig;
            float g = __expf(-0.5f * z * z) * norm;       // MUFU.EX2 fast path
            if (g != 0.0f)
                atomicAdd(out + ((size_t)b * WW + w) * DD + k, g);  // RED.E.ADD.F32
        }
    }
}

extern "C" void kernel_launch(void* const* d_in, const int* in_sizes, int n_in,
                              void* d_out, int out_size)
{
    const float* depth = (const float*)d_in[0];
    float* out = (float*)d_out;
    // zero the 4.1MB output via the driver's fill path (graph memset node);
    // the stream dependency orders it before the scatter kernel's atomics.
    cudaMemsetAsync(out, 0, (size_t)out_size * sizeof(float));
    dim_scatter_kernel<<<NB, NT>>>(depth, out);
}

// round 14
// speedup vs baseline: 1.0072x; 1.0072x over previous
#include <cuda_runtime.h>
#include <math.h>

// Problem constants (must match reference)
#define BB 16
#define HH 120
#define WW 160
#define DD 401              // int(8000/20)+1
#define WT 4                // w-tile per block
#define NT 384              // 12 warps -> 5 blocks/SM -> 640 blocks in ONE wave
#define NPIX (HH * WT)      // 480 pixels per block
#define NV4 ((WT * DD) / 4) // 401 float4 in the block's output span
#define DEPTH_MAX 8000.0f
#define INV_BIN   (1.0f / 20.0f)
#define BIN_SIZE  20.0f
#define ZERO_EPS  1e-06f
#define SIG_EPS   (0.5f + 1e-08f)

// fp32 sparsity: the Gaussian underflows to exactly 0 unless |k*20 - d| < ~7.2;
// bins are 20 apart -> only the rounded-nearest bin k = round(d/20) can be
// nonzero. For valid d in (eps, 8000], k is in [0,400]: no clamp needed.
// (d > eps && d <= max) also rejects NaN/Inf.
//
// FINAL (measured optimum): each block owns out[b, w0..w0+3, :] EXCLUSIVELY.
// Zero that span in GMEM up front (stores overlap the depth LDG latency),
// one bar.sync (exec + membar.cta: zeros ordered before this block's atomics
// at L2), then fire-and-forget RED.E.ADD.F32 scatter. No smem, no second
// barrier, no post-sync store tail. Single graph node: the r13 split-node
// experiment showed per-NODE overhead dominates (pure scatter kernel 5.06us
// but bench 8.96us with a memset node attached).
//
// Calibration record (kernel-side, ncu):
//   grid: 2560 blks 7.0 | 640 blks 5.34(x2) | 160 blks 5.92 | split-node 5.06+memset
//   NT (grid=640): 256: 5.92 | 384: 5.34 | 512(two waves): 5.70
//   exp2f / unguarded-RED: 6.05 (regress); identical-source spread +-0.5us.
//   All pipes <24% of peak: plateau = launch/ramp overhead.

__global__ void __launch_bounds__(NT)
dim_hist_kernel(const float* __restrict__ depth, float* __restrict__ out)
{
    const int blk = blockIdx.x;              // 0 .. 639
    const int b   = blk / (WW / WT);
    const int w0  = (blk - b * (WW / WT)) * WT;
    const int tid = threadIdx.x;

    // ---- depth prefetch first: LDG latency overlaps the zeroing stores ----
    // pixel p -> h = p>>2, wi = p&3 ; consecutive tid -> consecutive w
    const float* dbase = depth + (size_t)b * HH * WW + w0;
    float d0 = -1.0f, d1 = -1.0f;
    d0 = __ldg(dbase + (tid >> 2) * WW + (tid & 3));            // tid < 480 always
    {
        int p2 = tid + NT;                                       // 384..767
        if (p2 < NPIX) d1 = __ldg(dbase + (p2 >> 2) * WW + (p2 & 3));
    }

    // ---- zero this block's private output span: 401 STG.128 ----
    float* ospan = out + ((size_t)b * WW + w0) * DD;             // 16B-aligned
    float4* o4 = (float4*)ospan;
    const float4 z4 = make_float4(0.f, 0.f, 0.f, 0.f);
    if (tid < NV4) o4[tid] = z4;
    if (tid + NT < NV4) o4[tid + NT] = z4;

    // hoisted atomic bases (pure ALU, overlaps LDG wait)
    float* abase0 = ospan + (tid & 3) * DD;
    float* abase1 = ospan + ((tid + NT) & 3) * DD;

    __syncthreads();   // exec + membar.cta: zeros visible before our atomics

    const float inv_sig = 1.0f / SIG_EPS;                 // 1/(sigma+eps)
    const float norm    = 0.3989422804014327f * inv_sig;  // 1/((sigma+eps)*sqrt(2pi))

    // ---- scatter: one EX2 + at most one no-return global atomic per pixel ----
    if (d0 > ZERO_EPS && d0 <= DEPTH_MAX) {
        int k   = __float2int_rn(d0 * INV_BIN);           // nearest bin, [0,400]
        float z = ((float)k * BIN_SIZE - d0) * inv_sig;
        float g = __expf(-0.5f * z * z) * norm;
        if (g != 0.0f) atomicAdd(abase0 + k, g);          // RED.E.ADD.F32
    }
    if (d1 > ZERO_EPS && d1 <= DEPTH_MAX) {
        int k   = __float2int_rn(d1 * INV_BIN);
        float z = ((float)k * BIN_SIZE - d1) * inv_sig;
        float g = __expf(-0.5f * z * z) * norm;
        if (g != 0.0f) atomicAdd(abase1 + k, g);
    }
}

extern "C" void kernel_launch(void* const* d_in, const int* in_sizes, int n_in,
                              void* d_out, int out_size)
{
    const float* depth = (const float*)d_in[0];
    float* out = (float*)d_out;
    dim_hist_kernel<<<(BB * WW) / WT, NT>>>(depth, out);
}

// round 15
// speedup vs baseline: 1.3462x; 1.3365x over previous
#include <cuda_runtime.h>
#include <math.h>

// Problem constants (must match reference)
#define BB 16
#define HH 120
#define WW 160
#define DD 401              // int(8000/20)+1
#define WT 4                // w-tile per block
#define NT 384              // 12 warps -> 5 blocks/SM -> 640 blocks in ONE wave
#define NPIX (HH * WT)      // 480 pixels per block
#define NV4 ((WT * DD) / 4) // 401 float4 in the block's output span
#define DEPTH_MAX 8000.0f
#define INV_BIN   (1.0f / 20.0f)
#define BIN_SIZE  20.0f
#define ZERO_EPS  1e-06f
#define SIG_EPS   (0.5f + 1e-08f)

// fp32 sparsity: the Gaussian underflows to exactly 0 unless |k*20 - d| < ~7.2;
// bins are 20 apart -> only the rounded-nearest bin k = round(d/20) can be
// nonzero. For valid d in (eps, 8000], k is in [0,400]: no clamp needed.
// (d > eps && d <= max) also rejects NaN/Inf.
//
// FINAL (measured optimum, held): each block owns out[b, w0..w0+3, :]
// EXCLUSIVELY. Zero that span in GMEM up front (stores overlap the depth LDG
// latency), one bar.sync (exec + membar.cta: zeros ordered before this
// block's atomics at L2), then fire-and-forget RED.E.ADD.F32 scatter.
// No smem, no second barrier, no post-sync store tail, single graph node.
//
// Complete calibration record (kernel-side, ncu; bench noise +-1us):
//   structure: smem-atomic 5.34 | gmem-RED 5.34/5.57(x3) | vectorized 5.47
//              | pure-scatter+memset-node 5.06 kernel but 8.96 bench (per-node
//                overhead dominates -> single node required)
//   grid: 2560: 7.0 | 640: 5.34 | 160: 5.92
//   NT (grid=640): 256: 5.92 | 384: 5.34 | 512(two waves): 5.70
//   exp2f / unguarded-RED: 6.05 (regress)
//   All pipes <24% of peak: plateau = launch/ramp overhead, not code.

__global__ void __launch_bounds__(NT)
dim_hist_kernel(const float* __restrict__ depth, float* __restrict__ out)
{
    const int blk = blockIdx.x;              // 0 .. 639
    const int b   = blk / (WW / WT);
    const int w0  = (blk - b * (WW / WT)) * WT;
    const int tid = threadIdx.x;

    // ---- depth prefetch first: LDG latency overlaps the zeroing stores ----
    // pixel p -> h = p>>2, wi = p&3 ; consecutive tid -> consecutive w
    const float* dbase = depth + (size_t)b * HH * WW + w0;
    float d0 = -1.0f, d1 = -1.0f;
    d0 = __ldg(dbase + (tid >> 2) * WW + (tid & 3));            // tid < 480 always
    {
        int p2 = tid + NT;                                       // 384..767
        if (p2 < NPIX) d1 = __ldg(dbase + (p2 >> 2) * WW + (p2 & 3));
    }

    // ---- zero this block's private output span: 401 STG.128 ----
    float* ospan = out + ((size_t)b * WW + w0) * DD;             // 16B-aligned
    float4* o4 = (float4*)ospan;
    const float4 z4 = make_float4(0.f, 0.f, 0.f, 0.f);
    if (tid < NV4) o4[tid] = z4;
    if (tid + NT < NV4) o4[tid + NT] = z4;

    // hoisted atomic bases (pure ALU, overlaps LDG wait)
    float* abase0 = ospan + (tid & 3) * DD;
    float* abase1 = ospan + ((tid + NT) & 3) * DD;

    __syncthreads();   // exec + membar.cta: zeros visible before our atomics

    const float inv_sig = 1.0f / SIG_EPS;                 // 1/(sigma+eps)
    const float norm    = 0.3989422804014327f * inv_sig;  // 1/((sigma+eps)*sqrt(2pi))

    // ---- scatter: one EX2 + at most one no-return global atomic per pixel ----
    if (d0 > ZERO_EPS && d0 <= DEPTH_MAX) {
        int k   = __float2int_rn(d0 * INV_BIN);           // nearest bin, [0,400]
        float z = ((float)k * BIN_SIZE - d0) * inv_sig;
        float g = __expf(-0.5f * z * z) * norm;
        if (g != 0.0f) atomicAdd(abase0 + k, g);          // RED.E.ADD.F32
    }
    if (d1 > ZERO_EPS && d1 <= DEPTH_MAX) {
        int k   = __float2int_rn(d1 * INV_BIN);
        float z = ((float)k * BIN_SIZE - d1) * inv_sig;
        float g = __expf(-0.5f * z * z) * norm;
        if (g != 0.0f) atomicAdd(abase1 + k, g);
    }
}

extern "C" void kernel_launch(void* const* d_in, const int* in_sizes, int n_in,
                              void* d_out, int out_size)
{
    const float* depth = (const float*)d_in[0];
    float* out = (float*)d_out;
    dim_hist_kernel<<<(BB * WW) / WT, NT>>>(depth, out);
}